// round 4
// baseline (speedup 1.0000x reference)
#include <cuda_runtime.h>
#include <cstdint>

#define BB 32
#define NN 16384
#define CC 256
#define DD 64
#define SS 7
#define HH 128
#define MROWS (BB*NN)
#define SCALE_ATTN 0.125f
#define EPS_ATTN 1e-6f
#define LN_EPS 1e-5f
#define NCHUNK 16
#define CHUNK (NN/NCHUNK)
#define PART_STRIDE 456

// ---------------- scratch (static device globals; no allocation) ----------------
__device__ float g_K[MROWS*DD];                    // 128 MB
__device__ float g_V[MROWS*DD];                    // 128 MB
__device__ float g_q[BB*SS*DD];
__device__ float g_part[BB*NCHUNK*PART_STRIDE];

// ---------------- f32x2 packed-FMA helpers (Blackwell FFMA2) ----------------
__device__ __forceinline__ unsigned long long pk2(float lo, float hi) {
    unsigned long long r;
    asm("mov.b64 %0, {%1, %2};" : "=l"(r) : "f"(lo), "f"(hi));
    return r;
}
__device__ __forceinline__ unsigned long long ffma2(unsigned long long a,
                                                    unsigned long long b,
                                                    unsigned long long c) {
    unsigned long long r;
    asm("fma.rn.f32x2 %0, %1, %2, %3;" : "=l"(r) : "l"(a), "l"(b), "l"(c));
    return r;
}
__device__ __forceinline__ float2 upk2(unsigned long long v) {
    float2 f;
    asm("mov.b64 {%0, %1}, %2;" : "=f"(f.x), "=f"(f.y) : "l"(v));
    return f;
}

__device__ __forceinline__ float sigmoidf_(float x) { return 1.0f / (1.0f + __expf(-x)); }

// ---------------- kernel 0: init slot state into d_out ----------------
__global__ void init_slots_kernel(const float* __restrict__ mu, float* __restrict__ out) {
    int i = blockIdx.x * 256 + threadIdx.x;
    if (i < BB * SS * DD) out[i] = mu[i];
}

// ---------------- kernel 1: fused LN + [K|V] projection (FFMA2-tiled SGEMM) ----------------
// C[m, 0:64] = k, C[m, 64:128] = v ; A = LN(inputs) applied on tile load.
__global__ void __launch_bounds__(256) proj_kernel(
    const float* __restrict__ X,
    const float* __restrict__ Wk, const float* __restrict__ Wv,
    const float* __restrict__ lng, const float* __restrict__ lnb)
{
    __shared__ float As[16][128];
    __shared__ float Bs[16][128];
    __shared__ float s_mean[128], s_rstd[128];
    __shared__ float s_g[256], s_b[256];

    const int tid  = threadIdx.x;
    const int warp = tid >> 5, lane = tid & 31;
    const int m0   = blockIdx.x * 128;

    s_g[tid] = lng[tid];
    s_b[tid] = lnb[tid];

    // LN stats: 16 passes, warp-per-row (8 rows/pass)
    #pragma unroll 1
    for (int p = 0; p < 16; p++) {
        int r = p * 8 + warp;
        const float* xr = X + (size_t)(m0 + r) * CC + lane * 8;
        float4 a  = *(const float4*)xr;
        float4 b4 = *(const float4*)(xr + 4);
        float s = a.x + a.y + a.z + a.w + b4.x + b4.y + b4.z + b4.w;
        float q = a.x*a.x + a.y*a.y + a.z*a.z + a.w*a.w
                + b4.x*b4.x + b4.y*b4.y + b4.z*b4.z + b4.w*b4.w;
        #pragma unroll
        for (int o = 16; o; o >>= 1) {
            s += __shfl_xor_sync(0xffffffffu, s, o);
            q += __shfl_xor_sync(0xffffffffu, q, o);
        }
        if (lane == 0) {
            float mu  = s * (1.f / 256.f);
            float var = q * (1.f / 256.f) - mu * mu;
            s_mean[r] = mu;
            s_rstd[r] = rsqrtf(var + LN_EPS);
        }
    }
    __syncthreads();

    // load roles
    const int ar = tid >> 1;             // A row (0..127)
    const int ac = (tid & 1) * 8;        // A col-in-tile base (0 or 8)
    const int brow = tid >> 4;           // B k-row (0..15)
    const int bn   = (tid & 15) * 8;     // B col base (0..120)
    const float* bptr = ((bn < 64) ? Wk : Wv) + (bn & 63);
    const float* aptr = X + (size_t)(m0 + ar) * CC + ac;

    const float a_mu = s_mean[ar];
    const float a_rs = s_rstd[ar];

    float4 la0, la1, lb0, lb1;
    la0 = *(const float4*)(aptr);
    la1 = *(const float4*)(aptr + 4);
    lb0 = *(const float4*)(bptr + brow * 64);
    lb1 = *(const float4*)(bptr + brow * 64 + 4);

    unsigned long long acc[8][4];
    #pragma unroll
    for (int i = 0; i < 8; i++)
        #pragma unroll
        for (int j = 0; j < 4; j++) acc[i][j] = 0ull;

    const int ty = tid >> 4, tx = tid & 15;

    #pragma unroll 1
    for (int kb = 0; kb < 16; kb++) {
        __syncthreads();
        // store tiles (LN applied to A here)
        {
            int c = kb * 16 + ac;
            As[ac + 0][ar] = (la0.x - a_mu) * a_rs * s_g[c + 0] + s_b[c + 0];
            As[ac + 1][ar] = (la0.y - a_mu) * a_rs * s_g[c + 1] + s_b[c + 1];
            As[ac + 2][ar] = (la0.z - a_mu) * a_rs * s_g[c + 2] + s_b[c + 2];
            As[ac + 3][ar] = (la0.w - a_mu) * a_rs * s_g[c + 3] + s_b[c + 3];
            As[ac + 4][ar] = (la1.x - a_mu) * a_rs * s_g[c + 4] + s_b[c + 4];
            As[ac + 5][ar] = (la1.y - a_mu) * a_rs * s_g[c + 5] + s_b[c + 5];
            As[ac + 6][ar] = (la1.z - a_mu) * a_rs * s_g[c + 6] + s_b[c + 6];
            As[ac + 7][ar] = (la1.w - a_mu) * a_rs * s_g[c + 7] + s_b[c + 7];
            *(float4*)&Bs[brow][bn]     = lb0;
            *(float4*)&Bs[brow][bn + 4] = lb1;
        }
        __syncthreads();
        // prefetch next slab (overlaps compute via scoreboard)
        if (kb < 15) {
            const float* ap = aptr + (kb + 1) * 16;
            la0 = *(const float4*)ap;
            la1 = *(const float4*)(ap + 4);
            const float* bp = bptr + ((kb + 1) * 16 + brow) * 64;
            lb0 = *(const float4*)bp;
            lb1 = *(const float4*)(bp + 4);
        }
        // compute 16 k-steps, 8x8 per thread, packed f32x2 FMAs
        #pragma unroll
        for (int kk = 0; kk < 16; kk++) {
            float4 a0 = *(const float4*)&As[kk][ty * 8];
            float4 a1 = *(const float4*)&As[kk][ty * 8 + 4];
            ulonglong2 bA = *(const ulonglong2*)&Bs[kk][tx * 8];
            ulonglong2 bB = *(const ulonglong2*)&Bs[kk][tx * 8 + 4];
            float av[8] = {a0.x, a0.y, a0.z, a0.w, a1.x, a1.y, a1.z, a1.w};
            unsigned long long bp4[4] = {bA.x, bA.y, bB.x, bB.y};
            #pragma unroll
            for (int i = 0; i < 8; i++) {
                unsigned long long ad = pk2(av[i], av[i]);
                #pragma unroll
                for (int j = 0; j < 4; j++)
                    acc[i][j] = ffma2(ad, bp4[j], acc[i][j]);
            }
        }
    }

    // epilogue: cols tx*8..tx*8+7 go to K (tx<8) or V (tx>=8)
    float* dstbase = (tx < 8) ? g_K : g_V;
    const int coloff = (tx & 7) * 8;
    #pragma unroll
    for (int i = 0; i < 8; i++) {
        int row = m0 + ty * 8 + i;
        float2 c0 = upk2(acc[i][0]);
        float2 c1 = upk2(acc[i][1]);
        float2 c2 = upk2(acc[i][2]);
        float2 c3 = upk2(acc[i][3]);
        float* d = dstbase + (size_t)row * DD + coloff;
        *(float4*)d       = make_float4(c0.x, c0.y, c1.x, c1.y);
        *(float4*)(d + 4) = make_float4(c2.x, c2.y, c3.x, c3.y);
    }
}

// ---------------- kernel 2: per-iteration q projection (LN(slot) @ Wq / bWq) ----------------
__global__ void __launch_bounds__(256) q_kernel(
    const float* __restrict__ slots,
    const float* __restrict__ qlg, const float* __restrict__ qlb,
    const float* __restrict__ Wq,
    const float* __restrict__ bqlg, const float* __restrict__ bqlb,
    const float* __restrict__ bWq)
{
    __shared__ float xs[8][64];
    const int tid = threadIdx.x, lane = tid & 31, ws = tid >> 5;
    const int wid = blockIdx.x * 8 + ws;          // 0..223 == b*7+m
    const int m = wid % SS;

    const float* x = slots + wid * DD;
    float x0 = x[lane], x1 = x[lane + 32];
    float s = x0 + x1, q = x0 * x0 + x1 * x1;
    #pragma unroll
    for (int o = 16; o; o >>= 1) {
        s += __shfl_xor_sync(0xffffffffu, s, o);
        q += __shfl_xor_sync(0xffffffffu, q, o);
    }
    float mu = s * (1.f / 64.f);
    float rs = rsqrtf(q * (1.f / 64.f) - mu * mu + LN_EPS);

    const float* lg = (m < 6) ? qlg : bqlg;
    const float* lb = (m < 6) ? qlb : bqlb;
    const float* W  = (m < 6) ? Wq  : bWq;

    xs[ws][lane]      = (x0 - mu) * rs * lg[lane]      + lb[lane];
    xs[ws][lane + 32] = (x1 - mu) * rs * lg[lane + 32] + lb[lane + 32];
    __syncwarp();

    float q0 = 0.f, q1 = 0.f;
    #pragma unroll
    for (int e = 0; e < 64; e++) {
        float xe = xs[ws][e];
        q0 += xe * W[e * 64 + lane];
        q1 += xe * W[e * 64 + lane + 32];
    }
    g_q[wid * DD + lane]      = q0;
    g_q[wid * DD + lane + 32] = q1;
}

// ---------------- kernel 3: attention pass — logits/softmax/accumulate U, csum ----------------
// warp processes 4 rows (8 lanes per row), deterministic per-block partials
__global__ void __launch_bounds__(256) attn_kernel(float* __restrict__ part)
{
    const int b = blockIdx.y;
    const int chunk = blockIdx.x;
    __shared__ float qs[SS * DD];
    __shared__ float Uw[8][PART_STRIDE];
    const int tid = threadIdx.x;
    for (int i = tid; i < SS * DD; i += 256) qs[i] = g_q[b * SS * DD + i];
    __syncthreads();

    const int lane = tid & 31, warp = tid >> 5;
    const int g = lane >> 3;   // row within group-of-4
    const int j = lane & 7;    // d-slice owner (8 floats)

    float Up[SS][8];
    #pragma unroll
    for (int m = 0; m < SS; m++)
        #pragma unroll
        for (int e = 0; e < 8; e++) Up[m][e] = 0.f;
    float cs[SS] = {0.f, 0.f, 0.f, 0.f, 0.f, 0.f, 0.f};

    const float* Kb = g_K + (size_t)b * NN * DD;
    const float* Vb = g_V + (size_t)b * NN * DD;
    const int base = chunk * CHUNK + warp * 4 + g;

    #pragma unroll 1
    for (int s = 0; s < 32; s++) {
        int n = base + s * 32;
        const float* kp = Kb + (size_t)n * DD + j * 8;
        float4 k0 = *(const float4*)kp;
        float4 k1 = *(const float4*)(kp + 4);
        const float* vp = Vb + (size_t)n * DD + j * 8;
        float4 v0 = *(const float4*)vp;
        float4 v1 = *(const float4*)(vp + 4);

        float l[SS];
        #pragma unroll
        for (int m = 0; m < SS; m++) {
            const float* qm = qs + m * DD + j * 8;
            float p = k0.x*qm[0] + k0.y*qm[1] + k0.z*qm[2] + k0.w*qm[3]
                    + k1.x*qm[4] + k1.y*qm[5] + k1.z*qm[6] + k1.w*qm[7];
            p += __shfl_xor_sync(0xffffffffu, p, 1);
            p += __shfl_xor_sync(0xffffffffu, p, 2);
            p += __shfl_xor_sync(0xffffffffu, p, 4);
            l[m] = p * SCALE_ATTN;
        }
        float mx = l[0];
        #pragma unroll
        for (int m = 1; m < SS; m++) mx = fmaxf(mx, l[m]);
        float e7[SS], se = 0.f;
        #pragma unroll
        for (int m = 0; m < SS; m++) { e7[m] = __expf(l[m] - mx); se += e7[m]; }
        float inv = 1.0f / se;
        #pragma unroll
        for (int m = 0; m < SS; m++) {
            float a = e7[m] * inv + EPS_ATTN;
            cs[m] += a;
            Up[m][0] += a * v0.x; Up[m][1] += a * v0.y;
            Up[m][2] += a * v0.z; Up[m][3] += a * v0.w;
            Up[m][4] += a * v1.x; Up[m][5] += a * v1.y;
            Up[m][6] += a * v1.z; Up[m][7] += a * v1.w;
        }
    }

    // reduce across the 4 row-groups within the warp (j preserved)
    #pragma unroll
    for (int m = 0; m < SS; m++) {
        #pragma unroll
        for (int e = 0; e < 8; e++) {
            float t = Up[m][e];
            t += __shfl_xor_sync(0xffffffffu, t, 8);
            t += __shfl_xor_sync(0xffffffffu, t, 16);
            Up[m][e] = t;
        }
        float c = cs[m];
        c += __shfl_xor_sync(0xffffffffu, c, 8);
        c += __shfl_xor_sync(0xffffffffu, c, 16);
        cs[m] = c;
    }
    if (lane < 8) {
        #pragma unroll
        for (int m = 0; m < SS; m++)
            #pragma unroll
            for (int e = 0; e < 8; e++)
                Uw[warp][m * DD + lane * 8 + e] = Up[m][e];
    }
    if (lane == 0) {
        #pragma unroll
        for (int m = 0; m < SS; m++) Uw[warp][448 + m] = cs[m];
    }
    __syncthreads();

    // deterministic fixed-order sum over the 8 warps
    float* dst = part + (size_t)(b * NCHUNK + chunk) * PART_STRIDE;
    for (int i = tid; i < 455; i += 256) {
        float acc = Uw[0][i];
        #pragma unroll
        for (int w = 1; w < 8; w++) acc += Uw[w][i];
        dst[i] = acc;
    }
}

// ---------------- kernel 4: slot update — normalize U, GRU, LN, MLP residual ----------------
__global__ void __launch_bounds__(128) update_kernel(
    float* __restrict__ slots,
    const float* __restrict__ Wih, const float* __restrict__ Whh,
    const float* __restrict__ bih, const float* __restrict__ bhh,
    const float* __restrict__ mlng, const float* __restrict__ mlnb,
    const float* __restrict__ mW1,  const float* __restrict__ mb1,
    const float* __restrict__ mW2,  const float* __restrict__ mb2,
    const float* __restrict__ bmlng, const float* __restrict__ bmlnb,
    const float* __restrict__ bmW1,  const float* __restrict__ bmb1,
    const float* __restrict__ bmW2,  const float* __restrict__ bmb2)
{
    const int b = blockIdx.y;
    const int s = blockIdx.x;          // 0..6 ; s==6 is the "bg" slot
    const int t = threadIdx.x;

    __shared__ float us[64], hs[64], gi[192], gh[192], hn[64], xn[64], hid[128];
    __shared__ float red[2];

    if (t < 64) {
        float ua = 0.f, ca = 0.f;
        #pragma unroll 1
        for (int c = 0; c < NCHUNK; c++) {
            const float* p = g_part + (size_t)(b * NCHUNK + c) * PART_STRIDE;
            ua += p[s * 64 + t];
            ca += p[448 + s];
        }
        us[t] = ua / ca;
        hs[t] = slots[(b * SS + s) * DD + t];
    }
    __syncthreads();

    // gi (from u) and gh (from h): 384 dot products of length 64
    for (int idx = t; idx < 384; idx += 128) {
        const bool isI = (idx < 192);
        const int oo = isI ? idx : (idx - 192);
        const float* W  = isI ? Wih : Whh;
        const float* xv = isI ? us : hs;
        float acc = isI ? bih[oo] : bhh[oo];
        #pragma unroll
        for (int e = 0; e < 64; e++) acc += xv[e] * W[oo * 64 + e];
        if (isI) gi[oo] = acc; else gh[oo] = acc;
    }
    __syncthreads();

    if (t < 64) {
        float r = sigmoidf_(gi[t] + gh[t]);
        float z = sigmoidf_(gi[64 + t] + gh[64 + t]);
        float n = tanhf(gi[128 + t] + r * gh[128 + t]);
        hn[t] = (1.0f - z) * n + z * hs[t];
    }
    __syncthreads();

    // LN stats over hn (warp 0)
    if (t < 32) {
        float a = hn[t], bv = hn[t + 32];
        float sm = a + bv, sq = a * a + bv * bv;
        #pragma unroll
        for (int o = 16; o; o >>= 1) {
            sm += __shfl_xor_sync(0xffffffffu, sm, o);
            sq += __shfl_xor_sync(0xffffffffu, sq, o);
        }
        if (t == 0) {
            float mu = sm * (1.f / 64.f);
            red[0] = mu;
            red[1] = rsqrtf(sq * (1.f / 64.f) - mu * mu + LN_EPS);
        }
    }
    __syncthreads();

    const float* lg = (s < 6) ? mlng : bmlng;
    const float* lb = (s < 6) ? mlnb : bmlnb;
    const float* W1 = (s < 6) ? mW1 : bmW1;
    const float* b1 = (s < 6) ? mb1 : bmb1;
    const float* W2 = (s < 6) ? mW2 : bmW2;
    const float* b2 = (s < 6) ? mb2 : bmb2;

    if (t < 64) xn[t] = (hn[t] - red[0]) * red[1] * lg[t] + lb[t];
    __syncthreads();

    {   // hidden layer: 128 outputs
        float h1 = b1[t];
        #pragma unroll
        for (int e = 0; e < 64; e++) h1 += xn[e] * W1[e * HH + t];
        hid[t] = fmaxf(h1, 0.f);
    }
    __syncthreads();

    if (t < 64) {
        float o = b2[t];
        #pragma unroll
        for (int jj = 0; jj < 128; jj++) o += hid[jj] * W2[jj * 64 + t];
        slots[(b * SS + s) * DD + t] = hn[t] + o;
    }
}

// ---------------- launcher ----------------
extern "C" void kernel_launch(void* const* d_in, const int* in_sizes, int n_in,
                              void* d_out, int out_size) {
    (void)in_sizes; (void)n_in; (void)out_size;
    const float* inputs   = (const float*)d_in[0];
    const float* slots_mu = (const float*)d_in[1];
    const float* ln_in_g  = (const float*)d_in[2];
    const float* ln_in_b  = (const float*)d_in[3];
    const float* Wk       = (const float*)d_in[4];
    const float* Wv       = (const float*)d_in[5];
    const float* q_ln_g   = (const float*)d_in[6];
    const float* q_ln_b   = (const float*)d_in[7];
    const float* Wq       = (const float*)d_in[8];
    const float* bq_ln_g  = (const float*)d_in[9];
    const float* bq_ln_b  = (const float*)d_in[10];
    const float* bWq      = (const float*)d_in[11];
    const float* gWih     = (const float*)d_in[12];
    const float* gWhh     = (const float*)d_in[13];
    const float* gbih     = (const float*)d_in[14];
    const float* gbhh     = (const float*)d_in[15];
    const float* mlng     = (const float*)d_in[16];
    const float* mlnb     = (const float*)d_in[17];
    const float* mW1      = (const float*)d_in[18];
    const float* mb1      = (const float*)d_in[19];
    const float* mW2      = (const float*)d_in[20];
    const float* mb2      = (const float*)d_in[21];
    const float* bmlng    = (const float*)d_in[22];
    const float* bmlnb    = (const float*)d_in[23];
    const float* bmW1     = (const float*)d_in[24];
    const float* bmb1     = (const float*)d_in[25];
    const float* bmW2     = (const float*)d_in[26];
    const float* bmb2     = (const float*)d_in[27];
    float* out = (float*)d_out;

    float* part;
    cudaGetSymbolAddress((void**)&part, g_part);

    init_slots_kernel<<<56, 256>>>(slots_mu, out);
    proj_kernel<<<MROWS / 128, 256>>>(inputs, Wk, Wv, ln_in_g, ln_in_b);

    for (int it = 0; it < 3; it++) {
        q_kernel<<<28, 256>>>(out, q_ln_g, q_ln_b, Wq, bq_ln_g, bq_ln_b, bWq);
        attn_kernel<<<dim3(NCHUNK, BB), 256>>>(part);
        update_kernel<<<dim3(SS, BB), 128>>>(out, gWih, gWhh, gbih, gbhh,
                                             mlng, mlnb, mW1, mb1, mW2, mb2,
                                             bmlng, bmlnb, bmW1, bmb1, bmW2, bmb2);
    }
}

// round 6
// speedup vs baseline: 1.4009x; 1.4009x over previous
#include <cuda_runtime.h>
#include <cuda_bf16.h>
#include <cstdint>

#define BB 32
#define NN 16384
#define CC 256
#define DD 64
#define SS 7
#define HH 128
#define MROWS (BB*NN)
#define SCALE_ATTN 0.125f
#define EPS_ATTN 1e-6f
#define LN_EPS 1e-5f
#define NCHUNK 16
#define CHUNK (NN/NCHUNK)
#define PART_STRIDE 456
#define APITCH 40   // bf16 row pitch (80B = 20 banks -> conflict-free frag loads)

// ---------------- scratch (static device globals; no allocation) ----------------
__device__ float g_K[MROWS*DD];                    // 128 MB
__device__ float g_V[MROWS*DD];                    // 128 MB
__device__ float g_q[BB*SS*DD];
__device__ float g_part[BB*NCHUNK*PART_STRIDE];
// pre-split weights bf16 hi/lo, plain row-major Wt[n][c], n in 0..127 (K|V), c in 0..255
__device__ __nv_bfloat16 g_WbHi[128*256];
__device__ __nv_bfloat16 g_WbLo[128*256];

__device__ __forceinline__ float sigmoidf_(float x) { return 1.0f / (1.0f + __expf(-x)); }

__device__ __forceinline__ void mma16816(float* d, const uint32_t* a, const uint32_t* b) {
    asm volatile(
        "mma.sync.aligned.m16n8k16.row.col.f32.bf16.bf16.f32 "
        "{%0,%1,%2,%3}, {%4,%5,%6,%7}, {%8,%9}, {%0,%1,%2,%3};"
        : "+f"(d[0]), "+f"(d[1]), "+f"(d[2]), "+f"(d[3])
        : "r"(a[0]), "r"(a[1]), "r"(a[2]), "r"(a[3]), "r"(b[0]), "r"(b[1]));
}

// ---------------- kernel 0: init slot state into d_out ----------------
__global__ void init_slots_kernel(const float* __restrict__ mu, float* __restrict__ out) {
    int i = blockIdx.x * 256 + threadIdx.x;
    if (i < BB * SS * DD) out[i] = mu[i];
}

// ---------------- kernel 0b: split [Wk|Wv]^T into bf16 hi/lo, row-major [n][c] ----------------
__global__ void wsplit_kernel(const float* __restrict__ Wk, const float* __restrict__ Wv) {
    int idx = blockIdx.x * 256 + threadIdx.x;
    if (idx >= 128 * 256) return;
    int n = idx >> 8;          // 0..127 (output col: 0-63 K, 64-127 V)
    int c = idx & 255;         // 0..255 (reduction dim)
    float w = (n < 64) ? Wk[c * 64 + n] : Wv[c * 64 + (n - 64)];
    __nv_bfloat16 hi = __float2bfloat16(w);
    __nv_bfloat16 lo = __float2bfloat16(w - __bfloat162float(hi));
    g_WbHi[n * 256 + c] = hi;
    g_WbLo[n * 256 + c] = lo;
}

// ---------------- kernel 1: LN + [K|V] projection via mma.sync bf16-split ----------------
// C[128 x 128] per CTA; A = LN(X[m0:m0+128, 0:256]), B = Wt (K-major, col-major for mma)
__global__ void __launch_bounds__(256) proj_mma_kernel(
    const float* __restrict__ X,
    const float* __restrict__ lng, const float* __restrict__ lnb)
{
    __shared__ __nv_bfloat16 Ah[128 * APITCH], Al[128 * APITCH];
    __shared__ __nv_bfloat16 Bh[128 * APITCH], Bl[128 * APITCH];
    __shared__ float s_mean[128], s_rstd[128], s_g[256], s_b[256];

    const int tid = threadIdx.x, wid = tid >> 5, lane = tid & 31;
    const int m0 = blockIdx.x * 128;

    s_g[tid] = lng[tid];
    s_b[tid] = lnb[tid];

    // ---- LN stats: warp per row, 16 rows per warp ----
    #pragma unroll 1
    for (int p = 0; p < 4; p++) {
        float sm[4], sq[4];
        #pragma unroll
        for (int i = 0; i < 4; i++) {
            int r = (p * 4 + i) * 8 + wid;
            const float* xr = X + (size_t)(m0 + r) * CC + lane * 8;
            float4 a  = *(const float4*)xr;
            float4 b4 = *(const float4*)(xr + 4);
            sm[i] = a.x + a.y + a.z + a.w + b4.x + b4.y + b4.z + b4.w;
            sq[i] = a.x*a.x + a.y*a.y + a.z*a.z + a.w*a.w
                  + b4.x*b4.x + b4.y*b4.y + b4.z*b4.z + b4.w*b4.w;
        }
        #pragma unroll
        for (int i = 0; i < 4; i++) {
            #pragma unroll
            for (int o = 16; o; o >>= 1) {
                sm[i] += __shfl_xor_sync(0xffffffffu, sm[i], o);
                sq[i] += __shfl_xor_sync(0xffffffffu, sq[i], o);
            }
            if (lane == 0) {
                int r = (p * 4 + i) * 8 + wid;
                float mu = sm[i] * (1.f / 256.f);
                s_mean[r] = mu;
                s_rstd[r] = rsqrtf(sq[i] * (1.f / 256.f) - mu * mu + LN_EPS);
            }
        }
    }
    __syncthreads();

    // per-thread load roles (same for every chunk)
    const int r   = tid >> 1;              // row 0..127 (A and B)
    const int seg = tid & 1;               // half selector
    const float mu = s_mean[r], rs = s_rstd[r];
    const float* xrow = X + (size_t)(m0 + r) * CC + seg * 16;
    const uint4* wHrow = (const uint4*)(g_WbHi + r * 256) + seg * 2;  // 2 uint4 per chunk-half
    const uint4* wLrow = (const uint4*)(g_WbLo + r * 256) + seg * 2;

    // mma roles
    const int mw = wid >> 1;               // warp m-tile (0..3): rows mw*32..+31
    const int nw = wid & 1;                // warp n-tile (0..1): cols nw*64..+63
    const int g  = lane >> 2, tg = lane & 3;

    float acc[2][8][4];
    #pragma unroll
    for (int mt = 0; mt < 2; mt++)
        #pragma unroll
        for (int nt = 0; nt < 8; nt++)
            #pragma unroll
            for (int e = 0; e < 4; e++) acc[mt][nt][e] = 0.f;

    // prefetch chunk 0
    float4 xv[4];
    uint4 bvh[2], bvl[2];
    #pragma unroll
    for (int i = 0; i < 4; i++) xv[i] = *(const float4*)(xrow + i * 4);
    bvh[0] = wHrow[0]; bvh[1] = wHrow[1];
    bvl[0] = wLrow[0]; bvl[1] = wLrow[1];

    #pragma unroll 1
    for (int kc = 0; kc < 8; kc++) {
        // ---- stage: LN + split A, copy B into smem ----
        {
            const int cb0 = seg * 16;
            #pragma unroll
            for (int i = 0; i < 4; i++) {
                int cb = cb0 + i * 4;
                int c = kc * 32 + cb;
                float y0 = fmaf((xv[i].x - mu) * rs, s_g[c + 0], s_b[c + 0]);
                float y1 = fmaf((xv[i].y - mu) * rs, s_g[c + 1], s_b[c + 1]);
                float y2 = fmaf((xv[i].z - mu) * rs, s_g[c + 2], s_b[c + 2]);
                float y3 = fmaf((xv[i].w - mu) * rs, s_g[c + 3], s_b[c + 3]);
                __nv_bfloat162 h01 = __float22bfloat162_rn(make_float2(y0, y1));
                __nv_bfloat162 h23 = __float22bfloat162_rn(make_float2(y2, y3));
                __nv_bfloat162 l01 = __float22bfloat162_rn(
                    make_float2(y0 - __low2float(h01), y1 - __high2float(h01)));
                __nv_bfloat162 l23 = __float22bfloat162_rn(
                    make_float2(y2 - __low2float(h23), y3 - __high2float(h23)));
                *(uint32_t*)&Ah[r * APITCH + cb]     = *(uint32_t*)&h01;
                *(uint32_t*)&Ah[r * APITCH + cb + 2] = *(uint32_t*)&h23;
                *(uint32_t*)&Al[r * APITCH + cb]     = *(uint32_t*)&l01;
                *(uint32_t*)&Al[r * APITCH + cb + 2] = *(uint32_t*)&l23;
            }
            // B: 16 bf16 per thread per buffer (one uint4 = 8 bf16, x2)
            *(uint4*)&Bh[r * APITCH + seg * 16]     = bvh[0];
            *(uint4*)&Bh[r * APITCH + seg * 16 + 8] = bvh[1];
            *(uint4*)&Bl[r * APITCH + seg * 16]     = bvl[0];
            *(uint4*)&Bl[r * APITCH + seg * 16 + 8] = bvl[1];
        }
        __syncthreads();

        // prefetch next chunk while tensor pipe works
        if (kc < 7) {
            #pragma unroll
            for (int i = 0; i < 4; i++)
                xv[i] = *(const float4*)(xrow + (kc + 1) * 32 + i * 4);
            bvh[0] = wHrow[(kc + 1) * 4 + 0]; bvh[1] = wHrow[(kc + 1) * 4 + 1];
            bvl[0] = wLrow[(kc + 1) * 4 + 0]; bvl[1] = wLrow[(kc + 1) * 4 + 1];
        }

        // ---- mma: 2 k16 steps ----
        #pragma unroll
        for (int ks = 0; ks < 2; ks++) {
            const int kb = ks * 16 + tg * 2;
            uint32_t ah[2][4], al[2][4];
            #pragma unroll
            for (int mt = 0; mt < 2; mt++) {
                int row0 = mw * 32 + mt * 16 + g;
                ah[mt][0] = *(const uint32_t*)&Ah[(row0    ) * APITCH + kb];
                ah[mt][1] = *(const uint32_t*)&Ah[(row0 + 8) * APITCH + kb];
                ah[mt][2] = *(const uint32_t*)&Ah[(row0    ) * APITCH + kb + 8];
                ah[mt][3] = *(const uint32_t*)&Ah[(row0 + 8) * APITCH + kb + 8];
                al[mt][0] = *(const uint32_t*)&Al[(row0    ) * APITCH + kb];
                al[mt][1] = *(const uint32_t*)&Al[(row0 + 8) * APITCH + kb];
                al[mt][2] = *(const uint32_t*)&Al[(row0    ) * APITCH + kb + 8];
                al[mt][3] = *(const uint32_t*)&Al[(row0 + 8) * APITCH + kb + 8];
            }
            #pragma unroll
            for (int nt = 0; nt < 8; nt++) {
                int ncol = nw * 64 + nt * 8 + g;
                uint32_t bh[2], bl[2];
                bh[0] = *(const uint32_t*)&Bh[ncol * APITCH + kb];
                bh[1] = *(const uint32_t*)&Bh[ncol * APITCH + kb + 8];
                bl[0] = *(const uint32_t*)&Bl[ncol * APITCH + kb];
                bl[1] = *(const uint32_t*)&Bl[ncol * APITCH + kb + 8];
                #pragma unroll
                for (int mt = 0; mt < 2; mt++) {
                    mma16816(acc[mt][nt], ah[mt], bh);
                    mma16816(acc[mt][nt], ah[mt], bl);
                    mma16816(acc[mt][nt], al[mt], bh);
                }
            }
        }
        __syncthreads();
    }

    // ---- epilogue ----
    float* dstbase = nw ? g_V : g_K;
    #pragma unroll
    for (int mt = 0; mt < 2; mt++) {
        int row0 = m0 + mw * 32 + mt * 16 + g;
        #pragma unroll
        for (int nt = 0; nt < 8; nt++) {
            int coll = nt * 8 + tg * 2;
            *(float2*)(dstbase + (size_t)row0 * DD + coll) =
                make_float2(acc[mt][nt][0], acc[mt][nt][1]);
            *(float2*)(dstbase + (size_t)(row0 + 8) * DD + coll) =
                make_float2(acc[mt][nt][2], acc[mt][nt][3]);
        }
    }
}

// ---------------- kernel 2: per-iteration q projection (LN(slot) @ Wq / bWq) ----------------
__global__ void __launch_bounds__(256) q_kernel(
    const float* __restrict__ slots,
    const float* __restrict__ qlg, const float* __restrict__ qlb,
    const float* __restrict__ Wq,
    const float* __restrict__ bqlg, const float* __restrict__ bqlb,
    const float* __restrict__ bWq)
{
    __shared__ float xs[8][64];
    const int tid = threadIdx.x, lane = tid & 31, ws = tid >> 5;
    const int wid = blockIdx.x * 8 + ws;          // 0..223 == b*7+m
    const int m = wid % SS;

    const float* x = slots + wid * DD;
    float x0 = x[lane], x1 = x[lane + 32];
    float s = x0 + x1, q = x0 * x0 + x1 * x1;
    #pragma unroll
    for (int o = 16; o; o >>= 1) {
        s += __shfl_xor_sync(0xffffffffu, s, o);
        q += __shfl_xor_sync(0xffffffffu, q, o);
    }
    float mu = s * (1.f / 64.f);
    float rs = rsqrtf(q * (1.f / 64.f) - mu * mu + LN_EPS);

    const float* lg = (m < 6) ? qlg : bqlg;
    const float* lb = (m < 6) ? qlb : bqlb;
    const float* W  = (m < 6) ? Wq  : bWq;

    xs[ws][lane]      = (x0 - mu) * rs * lg[lane]      + lb[lane];
    xs[ws][lane + 32] = (x1 - mu) * rs * lg[lane + 32] + lb[lane + 32];
    __syncwarp();

    float q0 = 0.f, q1 = 0.f;
    #pragma unroll
    for (int e = 0; e < 64; e++) {
        float xe = xs[ws][e];
        q0 += xe * W[e * 64 + lane];
        q1 += xe * W[e * 64 + lane + 32];
    }
    g_q[wid * DD + lane]      = q0;
    g_q[wid * DD + lane + 32] = q1;
}

// ---------------- kernel 3: attention pass — 16 lanes/row, 2 rows/warp ----------------
__global__ void __launch_bounds__(256, 2) attn_kernel(float* __restrict__ part)
{
    const int b = blockIdx.y;
    const int chunk = blockIdx.x;
    __shared__ float qs[SS * DD];
    __shared__ float Uw[8][PART_STRIDE];
    const int tid = threadIdx.x;
    for (int i = tid; i < SS * DD; i += 256) qs[i] = g_q[b * SS * DD + i];
    __syncthreads();

    const int lane = tid & 31, warp = tid >> 5;
    const int g = lane >> 4;   // row within group-of-2
    const int j = lane & 15;   // d-slice owner (4 floats)

    float Up[SS][4];
    #pragma unroll
    for (int m = 0; m < SS; m++)
        #pragma unroll
        for (int e = 0; e < 4; e++) Up[m][e] = 0.f;
    float cs[SS] = {0.f, 0.f, 0.f, 0.f, 0.f, 0.f, 0.f};

    const float* Kb = g_K + (size_t)b * NN * DD;
    const float* Vb = g_V + (size_t)b * NN * DD;
    const int base = chunk * CHUNK + warp * 2 + g;

    #pragma unroll 1
    for (int s = 0; s < CHUNK / 16; s++) {
        int n = base + s * 16;
        float4 k4 = __ldcs((const float4*)(Kb + (size_t)n * DD + j * 4));
        float4 v4 = __ldcs((const float4*)(Vb + (size_t)n * DD + j * 4));

        float l[SS];
        #pragma unroll
        for (int m = 0; m < SS; m++) {
            float4 qm = *(const float4*)(qs + m * DD + j * 4);
            float p = k4.x * qm.x + k4.y * qm.y + k4.z * qm.z + k4.w * qm.w;
            p += __shfl_xor_sync(0xffffffffu, p, 1);
            p += __shfl_xor_sync(0xffffffffu, p, 2);
            p += __shfl_xor_sync(0xffffffffu, p, 4);
            p += __shfl_xor_sync(0xffffffffu, p, 8);
            l[m] = p * SCALE_ATTN;
        }
        float mx = l[0];
        #pragma unroll
        for (int m = 1; m < SS; m++) mx = fmaxf(mx, l[m]);
        float e7[SS], se = 0.f;
        #pragma unroll
        for (int m = 0; m < SS; m++) { e7[m] = __expf(l[m] - mx); se += e7[m]; }
        float inv = 1.0f / se;
        #pragma unroll
        for (int m = 0; m < SS; m++) {
            float a = e7[m] * inv + EPS_ATTN;
            cs[m] += a;
            Up[m][0] += a * v4.x; Up[m][1] += a * v4.y;
            Up[m][2] += a * v4.z; Up[m][3] += a * v4.w;
        }
    }

    // reduce across the 2 row-groups within the warp (j preserved)
    #pragma unroll
    for (int m = 0; m < SS; m++) {
        #pragma unroll
        for (int e = 0; e < 4; e++) {
            float t = Up[m][e];
            t += __shfl_xor_sync(0xffffffffu, t, 16);
            Up[m][e] = t;
        }
        float c = cs[m];
        c += __shfl_xor_sync(0xffffffffu, c, 16);
        cs[m] = c;
    }
    if (lane < 16) {
        #pragma unroll
        for (int m = 0; m < SS; m++)
            #pragma unroll
            for (int e = 0; e < 4; e++)
                Uw[warp][m * DD + j * 4 + e] = Up[m][e];
    }
    if (lane == 0) {
        #pragma unroll
        for (int m = 0; m < SS; m++) Uw[warp][448 + m] = cs[m];
    }
    __syncthreads();

    // deterministic fixed-order sum over the 8 warps
    float* dst = part + (size_t)(b * NCHUNK + chunk) * PART_STRIDE;
    for (int i = tid; i < 455; i += 256) {
        float acc = Uw[0][i];
        #pragma unroll
        for (int w = 1; w < 8; w++) acc += Uw[w][i];
        dst[i] = acc;
    }
}

// ---------------- kernel 4: slot update — normalize U, GRU, LN, MLP residual ----------------
__global__ void __launch_bounds__(128) update_kernel(
    float* __restrict__ slots,
    const float* __restrict__ Wih, const float* __restrict__ Whh,
    const float* __restrict__ bih, const float* __restrict__ bhh,
    const float* __restrict__ mlng, const float* __restrict__ mlnb,
    const float* __restrict__ mW1,  const float* __restrict__ mb1,
    const float* __restrict__ mW2,  const float* __restrict__ mb2,
    const float* __restrict__ bmlng, const float* __restrict__ bmlnb,
    const float* __restrict__ bmW1,  const float* __restrict__ bmb1,
    const float* __restrict__ bmW2,  const float* __restrict__ bmb2)
{
    const int b = blockIdx.y;
    const int s = blockIdx.x;          // 0..6 ; s==6 is the "bg" slot
    const int t = threadIdx.x;

    __shared__ float us[64], hs[64], gi[192], gh[192], hn[64], xn[64], hid[128];
    __shared__ float red[2];

    if (t < 64) {
        float ua = 0.f, ca = 0.f;
        #pragma unroll 1
        for (int c = 0; c < NCHUNK; c++) {
            const float* p = g_part + (size_t)(b * NCHUNK + c) * PART_STRIDE;
            ua += p[s * 64 + t];
            ca += p[448 + s];
        }
        us[t] = ua / ca;
        hs[t] = slots[(b * SS + s) * DD + t];
    }
    __syncthreads();

    for (int idx = t; idx < 384; idx += 128) {
        const bool isI = (idx < 192);
        const int oo = isI ? idx : (idx - 192);
        const float* W  = isI ? Wih : Whh;
        const float* xv = isI ? us : hs;
        float acc = isI ? bih[oo] : bhh[oo];
        #pragma unroll
        for (int e = 0; e < 64; e++) acc += xv[e] * W[oo * 64 + e];
        if (isI) gi[oo] = acc; else gh[oo] = acc;
    }
    __syncthreads();

    if (t < 64) {
        float r = sigmoidf_(gi[t] + gh[t]);
        float z = sigmoidf_(gi[64 + t] + gh[64 + t]);
        float n = tanhf(gi[128 + t] + r * gh[128 + t]);
        hn[t] = (1.0f - z) * n + z * hs[t];
    }
    __syncthreads();

    if (t < 32) {
        float a = hn[t], bv = hn[t + 32];
        float sm = a + bv, sq = a * a + bv * bv;
        #pragma unroll
        for (int o = 16; o; o >>= 1) {
            sm += __shfl_xor_sync(0xffffffffu, sm, o);
            sq += __shfl_xor_sync(0xffffffffu, sq, o);
        }
        if (t == 0) {
            float mu = sm * (1.f / 64.f);
            red[0] = mu;
            red[1] = rsqrtf(sq * (1.f / 64.f) - mu * mu + LN_EPS);
        }
    }
    __syncthreads();

    const float* lg = (s < 6) ? mlng : bmlng;
    const float* lb = (s < 6) ? mlnb : bmlnb;
    const float* W1 = (s < 6) ? mW1 : bmW1;
    const float* b1 = (s < 6) ? mb1 : bmb1;
    const float* W2 = (s < 6) ? mW2 : bmW2;
    const float* b2 = (s < 6) ? mb2 : bmb2;

    if (t < 64) xn[t] = (hn[t] - red[0]) * red[1] * lg[t] + lb[t];
    __syncthreads();

    {
        float h1 = b1[t];
        #pragma unroll
        for (int e = 0; e < 64; e++) h1 += xn[e] * W1[e * HH + t];
        hid[t] = fmaxf(h1, 0.f);
    }
    __syncthreads();

    if (t < 64) {
        float o = b2[t];
        #pragma unroll
        for (int jj = 0; jj < 128; jj++) o += hid[jj] * W2[jj * 64 + t];
        slots[(b * SS + s) * DD + t] = hn[t] + o;
    }
}

// ---------------- launcher ----------------
extern "C" void kernel_launch(void* const* d_in, const int* in_sizes, int n_in,
                              void* d_out, int out_size) {
    (void)in_sizes; (void)n_in; (void)out_size;
    const float* inputs   = (const float*)d_in[0];
    const float* slots_mu = (const float*)d_in[1];
    const float* ln_in_g  = (const float*)d_in[2];
    const float* ln_in_b  = (const float*)d_in[3];
    const float* Wk       = (const float*)d_in[4];
    const float* Wv       = (const float*)d_in[5];
    const float* q_ln_g   = (const float*)d_in[6];
    const float* q_ln_b   = (const float*)d_in[7];
    const float* Wq       = (const float*)d_in[8];
    const float* bq_ln_g  = (const float*)d_in[9];
    const float* bq_ln_b  = (const float*)d_in[10];
    const float* bWq      = (const float*)d_in[11];
    const float* gWih     = (const float*)d_in[12];
    const float* gWhh     = (const float*)d_in[13];
    const float* gbih     = (const float*)d_in[14];
    const float* gbhh     = (const float*)d_in[15];
    const float* mlng     = (const float*)d_in[16];
    const float* mlnb     = (const float*)d_in[17];
    const float* mW1      = (const float*)d_in[18];
    const float* mb1      = (const float*)d_in[19];
    const float* mW2      = (const float*)d_in[20];
    const float* mb2      = (const float*)d_in[21];
    const float* bmlng    = (const float*)d_in[22];
    const float* bmlnb    = (const float*)d_in[23];
    const float* bmW1     = (const float*)d_in[24];
    const float* bmb1     = (const float*)d_in[25];
    const float* bmW2     = (const float*)d_in[26];
    const float* bmb2     = (const float*)d_in[27];
    float* out = (float*)d_out;

    float* part;
    cudaGetSymbolAddress((void**)&part, g_part);

    init_slots_kernel<<<56, 256>>>(slots_mu, out);
    wsplit_kernel<<<128, 256>>>(Wk, Wv);
    proj_mma_kernel<<<MROWS / 128, 256>>>(inputs, ln_in_g, ln_in_b);

    for (int it = 0; it < 3; it++) {
        q_kernel<<<28, 256>>>(out, q_ln_g, q_ln_b, Wq, bq_ln_g, bq_ln_b, bWq);
        attn_kernel<<<dim3(NCHUNK, BB), 256>>>(part);
        update_kernel<<<dim3(SS, BB), 128>>>(out, gWih, gWhh, gbih, gbhh,
                                             mlng, mlnb, mW1, mb1, mW2, mb2,
                                             bmlng, bmlnb, bmW1, bmb1, bmW2, bmb2);
    }
}

// round 7
// speedup vs baseline: 1.4309x; 1.0214x over previous
#include <cuda_runtime.h>
#include <cuda_bf16.h>
#include <cstdint>

#define BB 32
#define NN 16384
#define CC 256
#define DD 64
#define SS 7
#define HH 128
#define MROWS (BB*NN)
#define SCALE_ATTN 0.125f
#define EPS_ATTN 1e-6f
#define LN_EPS 1e-5f
#define NCHUNK 16
#define CHUNK (NN/NCHUNK)
#define PART_STRIDE 456
#define APITCH 40   // bf16 row pitch (80B: 16B-aligned rows, conflict-free ldmatrix)

// proj smem layout (dynamic): two chunk buffers of [Ah|Al|Bh|Bl], each 128x40 bf16
#define PJ_BUF    40960
#define PJ_AL     10240
#define PJ_BH     20480
#define PJ_BL     30720
#define PJ_PARAMS 81920
#define PJ_SMEM   84992

// ---------------- scratch (static device globals; no allocation) ----------------
__device__ float g_K[MROWS*DD];
__device__ float g_V[MROWS*DD];
__device__ float g_q[BB*SS*DD];
__device__ float g_part[BB*NCHUNK*PART_STRIDE];
__device__ __nv_bfloat16 g_WbHi[128*256];
__device__ __nv_bfloat16 g_WbLo[128*256];

__device__ __forceinline__ float sigmoidf_(float x) { return 1.0f / (1.0f + __expf(-x)); }

__device__ __forceinline__ uint32_t smem_u32(const void* p) {
    uint32_t a;
    asm("{ .reg .u64 t; cvta.to.shared.u64 t, %1; cvt.u32.u64 %0, t; }" : "=r"(a) : "l"(p));
    return a;
}
__device__ __forceinline__ void mma16816(float* d, const uint32_t* a, const uint32_t* b) {
    asm volatile(
        "mma.sync.aligned.m16n8k16.row.col.f32.bf16.bf16.f32 "
        "{%0,%1,%2,%3}, {%4,%5,%6,%7}, {%8,%9}, {%0,%1,%2,%3};"
        : "+f"(d[0]), "+f"(d[1]), "+f"(d[2]), "+f"(d[3])
        : "r"(a[0]), "r"(a[1]), "r"(a[2]), "r"(a[3]), "r"(b[0]), "r"(b[1]));
}
__device__ __forceinline__ void ldsm_x4(uint32_t* r, uint32_t addr) {
    asm volatile("ldmatrix.sync.aligned.m8n8.x4.shared.b16 {%0,%1,%2,%3}, [%4];"
        : "=r"(r[0]), "=r"(r[1]), "=r"(r[2]), "=r"(r[3]) : "r"(addr));
}

// ---------------- kernel 0: init slot state into d_out ----------------
__global__ void init_slots_kernel(const float* __restrict__ mu, float* __restrict__ out) {
    int i = blockIdx.x * 256 + threadIdx.x;
    if (i < BB * SS * DD) out[i] = mu[i];
}

// ---------------- kernel 0b: split [Wk|Wv]^T into bf16 hi/lo, row-major [n][c] ----------------
__global__ void wsplit_kernel(const float* __restrict__ Wk, const float* __restrict__ Wv) {
    int idx = blockIdx.x * 256 + threadIdx.x;
    if (idx >= 128 * 256) return;
    int n = idx >> 8;
    int c = idx & 255;
    float w = (n < 64) ? Wk[c * 64 + n] : Wv[c * 64 + (n - 64)];
    __nv_bfloat16 hi = __float2bfloat16(w);
    __nv_bfloat16 lo = __float2bfloat16(w - __bfloat162float(hi));
    g_WbHi[n * 256 + c] = hi;
    g_WbLo[n * 256 + c] = lo;
}

// ---------------- kernel 1: LN + [K|V] projection via mma.sync bf16-split ----------------
__global__ void __launch_bounds__(256) proj_mma_kernel(
    const float* __restrict__ X,
    const float* __restrict__ lng, const float* __restrict__ lnb)
{
    extern __shared__ char smem[];
    float* s_mean = (float*)(smem + PJ_PARAMS);
    float* s_rstd = (float*)(smem + PJ_PARAMS + 512);
    float* s_g    = (float*)(smem + PJ_PARAMS + 1024);
    float* s_b    = (float*)(smem + PJ_PARAMS + 2048);

    const int tid = threadIdx.x, wid = tid >> 5, lane = tid & 31;
    const int m0 = blockIdx.x * 128;
    const uint32_t sbase = smem_u32(smem);

    s_g[tid] = lng[tid];
    s_b[tid] = lnb[tid];

    // ---- LN stats ----
    #pragma unroll 1
    for (int p = 0; p < 4; p++) {
        float sm[4], sq[4];
        #pragma unroll
        for (int i = 0; i < 4; i++) {
            int r = (p * 4 + i) * 8 + wid;
            const float* xr = X + (size_t)(m0 + r) * CC + lane * 8;
            float4 a  = *(const float4*)xr;
            float4 b4 = *(const float4*)(xr + 4);
            sm[i] = a.x + a.y + a.z + a.w + b4.x + b4.y + b4.z + b4.w;
            sq[i] = a.x*a.x + a.y*a.y + a.z*a.z + a.w*a.w
                  + b4.x*b4.x + b4.y*b4.y + b4.z*b4.z + b4.w*b4.w;
        }
        #pragma unroll
        for (int i = 0; i < 4; i++) {
            #pragma unroll
            for (int o = 16; o; o >>= 1) {
                sm[i] += __shfl_xor_sync(0xffffffffu, sm[i], o);
                sq[i] += __shfl_xor_sync(0xffffffffu, sq[i], o);
            }
            if (lane == 0) {
                int r = (p * 4 + i) * 8 + wid;
                float mu = sm[i] * (1.f / 256.f);
                s_mean[r] = mu;
                s_rstd[r] = rsqrtf(sq[i] * (1.f / 256.f) - mu * mu + LN_EPS);
            }
        }
    }
    __syncthreads();

    // loader roles
    const int r   = tid >> 1;
    const int seg = tid & 1;
    const float mu = s_mean[r], rs = s_rstd[r];
    const float* xrow = X + (size_t)(m0 + r) * CC + seg * 16;
    const __nv_bfloat16* wHrow = g_WbHi + r * 256 + seg * 16;
    const __nv_bfloat16* wLrow = g_WbLo + r * 256 + seg * 16;

    // mma roles
    const int mw = wid >> 1, nw = wid & 1;
    const int g  = lane >> 2, tg = lane & 3;
    const int mat = lane >> 3, rb = lane & 7;
    const uint32_t aoff = (uint32_t)((mw*32 + rb + (mat & 1)*8) * APITCH + (mat >> 1)*8) * 2;
    const uint32_t boff = (uint32_t)((nw*64 + rb) * APITCH + mat*8) * 2;

    float acc[2][8][4];
    #pragma unroll
    for (int mt = 0; mt < 2; mt++)
        #pragma unroll
        for (int nt = 0; nt < 8; nt++)
            #pragma unroll
            for (int e = 0; e < 4; e++) acc[mt][nt][e] = 0.f;

    float4 xv[4];
    uint4 bvh[2], bvl[2];

    // prologue: load chunk0 regs, stage buf0, load chunk1 regs
    #pragma unroll
    for (int i = 0; i < 4; i++) xv[i] = *(const float4*)(xrow + i * 4);
    bvh[0] = *(const uint4*)(wHrow);     bvh[1] = *(const uint4*)(wHrow + 8);
    bvl[0] = *(const uint4*)(wLrow);     bvl[1] = *(const uint4*)(wLrow + 8);

    {   // stage chunk 0 -> buf 0
        char* Ah = smem;            char* Al = smem + PJ_AL;
        char* Bh = smem + PJ_BH;    char* Bl = smem + PJ_BL;
        #pragma unroll
        for (int i = 0; i < 4; i++) {
            int cb = seg * 16 + i * 4;
            int c  = cb;
            float y0 = fmaf((xv[i].x - mu) * rs, s_g[c+0], s_b[c+0]);
            float y1 = fmaf((xv[i].y - mu) * rs, s_g[c+1], s_b[c+1]);
            float y2 = fmaf((xv[i].z - mu) * rs, s_g[c+2], s_b[c+2]);
            float y3 = fmaf((xv[i].w - mu) * rs, s_g[c+3], s_b[c+3]);
            __nv_bfloat162 h01 = __float22bfloat162_rn(make_float2(y0, y1));
            __nv_bfloat162 h23 = __float22bfloat162_rn(make_float2(y2, y3));
            __nv_bfloat162 l01 = __float22bfloat162_rn(make_float2(y0 - __low2float(h01), y1 - __high2float(h01)));
            __nv_bfloat162 l23 = __float22bfloat162_rn(make_float2(y2 - __low2float(h23), y3 - __high2float(h23)));
            uint2 uh = make_uint2(*(uint32_t*)&h01, *(uint32_t*)&h23);
            uint2 ul = make_uint2(*(uint32_t*)&l01, *(uint32_t*)&l23);
            *(uint2*)(Ah + r * 80 + cb * 2) = uh;
            *(uint2*)(Al + r * 80 + cb * 2) = ul;
        }
        *(uint4*)(Bh + r * 80 + seg * 32)      = bvh[0];
        *(uint4*)(Bh + r * 80 + seg * 32 + 16) = bvh[1];
        *(uint4*)(Bl + r * 80 + seg * 32)      = bvl[0];
        *(uint4*)(Bl + r * 80 + seg * 32 + 16) = bvl[1];
    }
    #pragma unroll
    for (int i = 0; i < 4; i++) xv[i] = *(const float4*)(xrow + 32 + i * 4);
    bvh[0] = *(const uint4*)(wHrow + 32); bvh[1] = *(const uint4*)(wHrow + 40);
    bvl[0] = *(const uint4*)(wLrow + 32); bvl[1] = *(const uint4*)(wLrow + 40);
    __syncthreads();

    #pragma unroll 1
    for (int kc = 0; kc < 8; kc++) {
        const uint32_t bufo = (uint32_t)(kc & 1) * PJ_BUF;

        // ---- stage chunk kc+1 into the other buffer (regs loaded last iter) ----
        if (kc < 7) {
            uint32_t nb = (uint32_t)((kc + 1) & 1) * PJ_BUF;
            char* Ah = smem + nb;            char* Al = smem + nb + PJ_AL;
            char* Bh = smem + nb + PJ_BH;    char* Bl = smem + nb + PJ_BL;
            #pragma unroll
            for (int i = 0; i < 4; i++) {
                int cb = seg * 16 + i * 4;
                int c  = (kc + 1) * 32 + cb;
                float y0 = fmaf((xv[i].x - mu) * rs, s_g[c+0], s_b[c+0]);
                float y1 = fmaf((xv[i].y - mu) * rs, s_g[c+1], s_b[c+1]);
                float y2 = fmaf((xv[i].z - mu) * rs, s_g[c+2], s_b[c+2]);
                float y3 = fmaf((xv[i].w - mu) * rs, s_g[c+3], s_b[c+3]);
                __nv_bfloat162 h01 = __float22bfloat162_rn(make_float2(y0, y1));
                __nv_bfloat162 h23 = __float22bfloat162_rn(make_float2(y2, y3));
                __nv_bfloat162 l01 = __float22bfloat162_rn(make_float2(y0 - __low2float(h01), y1 - __high2float(h01)));
                __nv_bfloat162 l23 = __float22bfloat162_rn(make_float2(y2 - __low2float(h23), y3 - __high2float(h23)));
                uint2 uh = make_uint2(*(uint32_t*)&h01, *(uint32_t*)&h23);
                uint2 ul = make_uint2(*(uint32_t*)&l01, *(uint32_t*)&l23);
                *(uint2*)(Ah + r * 80 + cb * 2) = uh;
                *(uint2*)(Al + r * 80 + cb * 2) = ul;
            }
            *(uint4*)(Bh + r * 80 + seg * 32)      = bvh[0];
            *(uint4*)(Bh + r * 80 + seg * 32 + 16) = bvh[1];
            *(uint4*)(Bl + r * 80 + seg * 32)      = bvl[0];
            *(uint4*)(Bl + r * 80 + seg * 32 + 16) = bvl[1];
        }
        // ---- prefetch chunk kc+2 from global ----
        if (kc < 6) {
            const float* xp = xrow + (kc + 2) * 32;
            #pragma unroll
            for (int i = 0; i < 4; i++) xv[i] = *(const float4*)(xp + i * 4);
            const __nv_bfloat16* wh = wHrow + (kc + 2) * 32;
            const __nv_bfloat16* wl = wLrow + (kc + 2) * 32;
            bvh[0] = *(const uint4*)(wh); bvh[1] = *(const uint4*)(wh + 8);
            bvl[0] = *(const uint4*)(wl); bvl[1] = *(const uint4*)(wl + 8);
        }

        // ---- MMA over current buffer via ldmatrix ----
        {
            const uint32_t aH = sbase + bufo + aoff;
            const uint32_t aL = aH + PJ_AL;
            const uint32_t bH = sbase + bufo + PJ_BH + boff;
            const uint32_t bL = bH + (PJ_BL - PJ_BH);

            uint32_t ah[2][2][4], al[2][2][4];
            #pragma unroll
            for (int mt = 0; mt < 2; mt++)
                #pragma unroll
                for (int ks = 0; ks < 2; ks++) {
                    ldsm_x4(ah[mt][ks], aH + mt * 1280 + ks * 32);
                    ldsm_x4(al[mt][ks], aL + mt * 1280 + ks * 32);
                }
            #pragma unroll
            for (int nt = 0; nt < 8; nt++) {
                uint32_t bh[4], bl[4];
                ldsm_x4(bh, bH + nt * 640);
                ldsm_x4(bl, bL + nt * 640);
                #pragma unroll
                for (int ks = 0; ks < 2; ks++) {
                    #pragma unroll
                    for (int mt = 0; mt < 2; mt++) {
                        mma16816(acc[mt][nt], ah[mt][ks], &bh[ks * 2]);
                        mma16816(acc[mt][nt], ah[mt][ks], &bl[ks * 2]);
                        mma16816(acc[mt][nt], al[mt][ks], &bh[ks * 2]);
                    }
                }
            }
        }
        __syncthreads();
    }

    // ---- epilogue ----
    float* dstbase = nw ? g_V : g_K;
    #pragma unroll
    for (int mt = 0; mt < 2; mt++) {
        int row0 = m0 + mw * 32 + mt * 16 + g;
        #pragma unroll
        for (int nt = 0; nt < 8; nt++) {
            int coll = nt * 8 + tg * 2;
            *(float2*)(dstbase + (size_t)row0 * DD + coll) =
                make_float2(acc[mt][nt][0], acc[mt][nt][1]);
            *(float2*)(dstbase + (size_t)(row0 + 8) * DD + coll) =
                make_float2(acc[mt][nt][2], acc[mt][nt][3]);
        }
    }
}

// ---------------- kernel 2: iteration-0 q projection ----------------
__global__ void __launch_bounds__(256) q_kernel(
    const float* __restrict__ slots,
    const float* __restrict__ qlg, const float* __restrict__ qlb,
    const float* __restrict__ Wq,
    const float* __restrict__ bqlg, const float* __restrict__ bqlb,
    const float* __restrict__ bWq)
{
    __shared__ float xs[8][64];
    const int tid = threadIdx.x, lane = tid & 31, ws = tid >> 5;
    const int wid = blockIdx.x * 8 + ws;
    const int m = wid % SS;

    const float* x = slots + wid * DD;
    float x0 = x[lane], x1 = x[lane + 32];
    float s = x0 + x1, q = x0 * x0 + x1 * x1;
    #pragma unroll
    for (int o = 16; o; o >>= 1) {
        s += __shfl_xor_sync(0xffffffffu, s, o);
        q += __shfl_xor_sync(0xffffffffu, q, o);
    }
    float mu = s * (1.f / 64.f);
    float rs = rsqrtf(q * (1.f / 64.f) - mu * mu + LN_EPS);

    const float* lg = (m < 6) ? qlg : bqlg;
    const float* lb = (m < 6) ? qlb : bqlb;
    const float* W  = (m < 6) ? Wq  : bWq;

    xs[ws][lane]      = (x0 - mu) * rs * lg[lane]      + lb[lane];
    xs[ws][lane + 32] = (x1 - mu) * rs * lg[lane + 32] + lb[lane + 32];
    __syncwarp();

    float q0 = 0.f, q1 = 0.f;
    #pragma unroll
    for (int e = 0; e < 64; e++) {
        float xe = xs[ws][e];
        q0 += xe * W[e * 64 + lane];
        q1 += xe * W[e * 64 + lane + 32];
    }
    g_q[wid * DD + lane]      = q0;
    g_q[wid * DD + lane + 32] = q1;
}

// ---------------- kernel 3: attention pass — 16 lanes/row, 2 rows/warp, 2-way n ILP ----------------
__global__ void __launch_bounds__(256, 2) attn_kernel(float* __restrict__ part)
{
    const int b = blockIdx.y;
    const int chunk = blockIdx.x;
    __shared__ float qs[SS * DD];
    __shared__ float Uw[8][PART_STRIDE];
    const int tid = threadIdx.x;
    for (int i = tid; i < SS * DD; i += 256) qs[i] = g_q[b * SS * DD + i];
    __syncthreads();

    const int lane = tid & 31, warp = tid >> 5;
    const int g = lane >> 4;
    const int j = lane & 15;

    float Up[SS][4];
    #pragma unroll
    for (int m = 0; m < SS; m++)
        #pragma unroll
        for (int e = 0; e < 4; e++) Up[m][e] = 0.f;
    float cs[SS] = {0.f, 0.f, 0.f, 0.f, 0.f, 0.f, 0.f};

    const float* Kb = g_K + (size_t)b * NN * DD;
    const float* Vb = g_V + (size_t)b * NN * DD;
    const int base = chunk * CHUNK + warp * 2 + g;

    #pragma unroll 1
    for (int s = 0; s < CHUNK / 32; s++) {
        int na = base + s * 16;
        int nb2 = na + (CHUNK / 2);
        float4 ka = __ldcs((const float4*)(Kb + (size_t)na * DD + j * 4));
        float4 va = __ldcs((const float4*)(Vb + (size_t)na * DD + j * 4));
        float4 kb = __ldcs((const float4*)(Kb + (size_t)nb2 * DD + j * 4));
        float4 vb = __ldcs((const float4*)(Vb + (size_t)nb2 * DD + j * 4));

        float la[SS], lb_[SS];
        #pragma unroll
        for (int m = 0; m < SS; m++) {
            float4 qm = *(const float4*)(qs + m * DD + j * 4);
            float pa = ka.x * qm.x + ka.y * qm.y + ka.z * qm.z + ka.w * qm.w;
            float pb = kb.x * qm.x + kb.y * qm.y + kb.z * qm.z + kb.w * qm.w;
            #pragma unroll
            for (int o = 1; o < 16; o <<= 1) {
                pa += __shfl_xor_sync(0xffffffffu, pa, o);
                pb += __shfl_xor_sync(0xffffffffu, pb, o);
            }
            la[m]  = pa * SCALE_ATTN;
            lb_[m] = pb * SCALE_ATTN;
        }
        float mxa = la[0], mxb = lb_[0];
        #pragma unroll
        for (int m = 1; m < SS; m++) { mxa = fmaxf(mxa, la[m]); mxb = fmaxf(mxb, lb_[m]); }
        float ea[SS], eb[SS], sa = 0.f, sb2 = 0.f;
        #pragma unroll
        for (int m = 0; m < SS; m++) {
            ea[m] = __expf(la[m] - mxa);  sa  += ea[m];
            eb[m] = __expf(lb_[m] - mxb); sb2 += eb[m];
        }
        float inva = 1.0f / sa, invb = 1.0f / sb2;
        #pragma unroll
        for (int m = 0; m < SS; m++) {
            float aa = ea[m] * inva + EPS_ATTN;
            float ab = eb[m] * invb + EPS_ATTN;
            cs[m] += aa + ab;
            Up[m][0] += aa * va.x + ab * vb.x;
            Up[m][1] += aa * va.y + ab * vb.y;
            Up[m][2] += aa * va.z + ab * vb.z;
            Up[m][3] += aa * va.w + ab * vb.w;
        }
    }

    #pragma unroll
    for (int m = 0; m < SS; m++) {
        #pragma unroll
        for (int e = 0; e < 4; e++) {
            float t = Up[m][e];
            t += __shfl_xor_sync(0xffffffffu, t, 16);
            Up[m][e] = t;
        }
        float c = cs[m];
        c += __shfl_xor_sync(0xffffffffu, c, 16);
        cs[m] = c;
    }
    if (lane < 16) {
        #pragma unroll
        for (int m = 0; m < SS; m++)
            #pragma unroll
            for (int e = 0; e < 4; e++)
                Uw[warp][m * DD + j * 4 + e] = Up[m][e];
    }
    if (lane == 0) {
        #pragma unroll
        for (int m = 0; m < SS; m++) Uw[warp][448 + m] = cs[m];
    }
    __syncthreads();

    float* dst = part + (size_t)(b * NCHUNK + chunk) * PART_STRIDE;
    for (int i = tid; i < 455; i += 256) {
        float acc = Uw[0][i];
        #pragma unroll
        for (int w = 1; w < 8; w++) acc += Uw[w][i];
        dst[i] = acc;
    }
}

// ---------------- kernel 4: slot update + fused next-iter q projection ----------------
__global__ void __launch_bounds__(128) update_kernel(
    float* __restrict__ slots,
    const float* __restrict__ Wih, const float* __restrict__ Whh,
    const float* __restrict__ bih, const float* __restrict__ bhh,
    const float* __restrict__ mlng, const float* __restrict__ mlnb,
    const float* __restrict__ mW1,  const float* __restrict__ mb1,
    const float* __restrict__ mW2,  const float* __restrict__ mb2,
    const float* __restrict__ bmlng, const float* __restrict__ bmlnb,
    const float* __restrict__ bmW1,  const float* __restrict__ bmb1,
    const float* __restrict__ bmW2,  const float* __restrict__ bmb2,
    const float* __restrict__ qlg, const float* __restrict__ qlb,
    const float* __restrict__ Wq,
    const float* __restrict__ bqlg, const float* __restrict__ bqlb,
    const float* __restrict__ bWq)
{
    const int b = blockIdx.y;
    const int s = blockIdx.x;
    const int t = threadIdx.x;

    __shared__ float us[64], hs[64], gi[192], gh[192], hn[64], xn[64], hid[128], fin[64], xq[64];
    __shared__ float red[2], red2[2];

    if (t < 64) {
        float ua = 0.f, ca = 0.f;
        #pragma unroll 1
        for (int c = 0; c < NCHUNK; c++) {
            const float* p = g_part + (size_t)(b * NCHUNK + c) * PART_STRIDE;
            ua += p[s * 64 + t];
            ca += p[448 + s];
        }
        us[t] = ua / ca;
        hs[t] = slots[(b * SS + s) * DD + t];
    }
    __syncthreads();

    for (int idx = t; idx < 384; idx += 128) {
        const bool isI = (idx < 192);
        const int oo = isI ? idx : (idx - 192);
        const float* W  = isI ? Wih : Whh;
        const float* xv = isI ? us : hs;
        float acc = isI ? bih[oo] : bhh[oo];
        #pragma unroll
        for (int e = 0; e < 64; e++) acc += xv[e] * W[oo * 64 + e];
        if (isI) gi[oo] = acc; else gh[oo] = acc;
    }
    __syncthreads();

    if (t < 64) {
        float r = sigmoidf_(gi[t] + gh[t]);
        float z = sigmoidf_(gi[64 + t] + gh[64 + t]);
        float n = tanhf(gi[128 + t] + r * gh[128 + t]);
        hn[t] = (1.0f - z) * n + z * hs[t];
    }
    __syncthreads();

    if (t < 32) {
        float a = hn[t], bv = hn[t + 32];
        float sm = a + bv, sq = a * a + bv * bv;
        #pragma unroll
        for (int o = 16; o; o >>= 1) {
            sm += __shfl_xor_sync(0xffffffffu, sm, o);
            sq += __shfl_xor_sync(0xffffffffu, sq, o);
        }
        if (t == 0) {
            float mu = sm * (1.f / 64.f);
            red[0] = mu;
            red[1] = rsqrtf(sq * (1.f / 64.f) - mu * mu + LN_EPS);
        }
    }
    __syncthreads();

    const float* lg = (s < 6) ? mlng : bmlng;
    const float* lb = (s < 6) ? mlnb : bmlnb;
    const float* W1 = (s < 6) ? mW1 : bmW1;
    const float* b1 = (s < 6) ? mb1 : bmb1;
    const float* W2 = (s < 6) ? mW2 : bmW2;
    const float* b2 = (s < 6) ? mb2 : bmb2;

    if (t < 64) xn[t] = (hn[t] - red[0]) * red[1] * lg[t] + lb[t];
    __syncthreads();

    {
        float h1 = b1[t];
        #pragma unroll
        for (int e = 0; e < 64; e++) h1 += xn[e] * W1[e * HH + t];
        hid[t] = fmaxf(h1, 0.f);
    }
    __syncthreads();

    if (t < 64) {
        float o = b2[t];
        #pragma unroll
        for (int jj = 0; jj < 128; jj++) o += hid[jj] * W2[jj * 64 + t];
        float fv = hn[t] + o;
        slots[(b * SS + s) * DD + t] = fv;
        fin[t] = fv;
    }
    __syncthreads();

    // ---- fused q projection for next iteration ----
    if (t < 32) {
        float a = fin[t], bv = fin[t + 32];
        float sm = a + bv, sq = a * a + bv * bv;
        #pragma unroll
        for (int o = 16; o; o >>= 1) {
            sm += __shfl_xor_sync(0xffffffffu, sm, o);
            sq += __shfl_xor_sync(0xffffffffu, sq, o);
        }
        if (t == 0) {
            float mu = sm * (1.f / 64.f);
            red2[0] = mu;
            red2[1] = rsqrtf(sq * (1.f / 64.f) - mu * mu + LN_EPS);
        }
    }
    __syncthreads();

    const float* qg = (s < 6) ? qlg : bqlg;
    const float* qb = (s < 6) ? qlb : bqlb;
    const float* qW = (s < 6) ? Wq  : bWq;

    if (t < 64) xq[t] = (fin[t] - red2[0]) * red2[1] * qg[t] + qb[t];
    __syncthreads();

    if (t < 64) {
        float qv = 0.f;
        #pragma unroll
        for (int e = 0; e < 64; e++) qv += xq[e] * qW[e * 64 + t];
        g_q[(b * SS + s) * DD + t] = qv;
    }
}

// ---------------- launcher ----------------
extern "C" void kernel_launch(void* const* d_in, const int* in_sizes, int n_in,
                              void* d_out, int out_size) {
    (void)in_sizes; (void)n_in; (void)out_size;
    const float* inputs   = (const float*)d_in[0];
    const float* slots_mu = (const float*)d_in[1];
    const float* ln_in_g  = (const float*)d_in[2];
    const float* ln_in_b  = (const float*)d_in[3];
    const float* Wk       = (const float*)d_in[4];
    const float* Wv       = (const float*)d_in[5];
    const float* q_ln_g   = (const float*)d_in[6];
    const float* q_ln_b   = (const float*)d_in[7];
    const float* Wq       = (const float*)d_in[8];
    const float* bq_ln_g  = (const float*)d_in[9];
    const float* bq_ln_b  = (const float*)d_in[10];
    const float* bWq      = (const float*)d_in[11];
    const float* gWih     = (const float*)d_in[12];
    const float* gWhh     = (const float*)d_in[13];
    const float* gbih     = (const float*)d_in[14];
    const float* gbhh     = (const float*)d_in[15];
    const float* mlng     = (const float*)d_in[16];
    const float* mlnb     = (const float*)d_in[17];
    const float* mW1      = (const float*)d_in[18];
    const float* mb1      = (const float*)d_in[19];
    const float* mW2      = (const float*)d_in[20];
    const float* mb2      = (const float*)d_in[21];
    const float* bmlng    = (const float*)d_in[22];
    const float* bmlnb    = (const float*)d_in[23];
    const float* bmW1     = (const float*)d_in[24];
    const float* bmb1     = (const float*)d_in[25];
    const float* bmW2     = (const float*)d_in[26];
    const float* bmb2     = (const float*)d_in[27];
    float* out = (float*)d_out;

    float* part;
    cudaGetSymbolAddress((void**)&part, g_part);

    cudaFuncSetAttribute(proj_mma_kernel,
                         cudaFuncAttributeMaxDynamicSharedMemorySize, PJ_SMEM);

    init_slots_kernel<<<56, 256>>>(slots_mu, out);
    wsplit_kernel<<<128, 256>>>(Wk, Wv);
    proj_mma_kernel<<<MROWS / 128, 256, PJ_SMEM>>>(inputs, ln_in_g, ln_in_b);
    q_kernel<<<28, 256>>>(out, q_ln_g, q_ln_b, Wq, bq_ln_g, bq_ln_b, bWq);

    for (int it = 0; it < 3; it++) {
        attn_kernel<<<dim3(NCHUNK, BB), 256>>>(part);
        update_kernel<<<dim3(SS, BB), 128>>>(out, gWih, gWhh, gbih, gbhh,
                                             mlng, mlnb, mW1, mb1, mW2, mb2,
                                             bmlng, bmlnb, bmW1, bmb1, bmW2, bmb2,
                                             q_ln_g, q_ln_b, Wq, bq_ln_g, bq_ln_b, bWq);
    }
}